// round 1
// baseline (speedup 1.0000x reference)
#include <cuda_runtime.h>
#include <math.h>

// Problem constants
#define B_SZ   8
#define H_IN   14
#define W_IN   14
#define HP     12
#define WP     12
#define ISZ    144        // 9 * 16 input capsules per position
#define OSZ    16
#define PSZ    16         // 4x4 pose
#define NPOS   (B_SZ * HP * WP)   // 1152
#define VSTRIDE 260       // padded i-stride for votes (260 % 32 == 4 -> conflict-free f4 reads)
#define EPSF   1e-9f

struct Smem {
    float votes[ISZ * VSTRIDE];   // [144][260] (only first 256 used per row)  149760 B
    float rr[ISZ * OSZ];          // routing coefficients                        9216 B
    float rp[ISZ * OSZ];          // rr * i_act                                  9216 B
    float pose[ISZ * PSZ];        // input pose patch                            9216 B
    float act[ISZ];               // input activations                            576 B
    float mean[OSZ * PSZ];        //                                             1024 B
    float inv2var[OSZ * PSZ];     // 1/(2*sigma^2+eps)                           1024 B
    float logact[OSZ];
    float slog[OSZ];              // sum_p log(sigma+eps)
    float oact[OSZ];
};
// total ~180,416 B < 227 KB dynamic smem limit

__global__ void __launch_bounds__(256, 1)
capsconv_em_kernel(const float* __restrict__ pose_in,   // [8,14,14,256]
                   const float* __restrict__ act_in,    // [8,14,14,16]
                   const float* __restrict__ w,         // [144,16,4,4]
                   const float* __restrict__ beta_v,    // [16]
                   const float* __restrict__ beta_a,    // [16]
                   float* __restrict__ out)             // pose [1152*256] ++ act [1152*16]
{
    extern __shared__ char smem_raw[];
    Smem& sm = *reinterpret_cast<Smem*>(smem_raw);

    const int tid = threadIdx.x;
    const int n   = blockIdx.x;
    const int b   = n / (HP * WP);
    const int rem = n % (HP * WP);
    const int y   = rem / WP;
    const int x   = rem % WP;

    // ---- Load pose patch into SMEM (float4, coalesced) ----
    for (int idx = tid; idx < ISZ * 4; idx += 256) {     // 576 float4
        int i  = idx >> 2;
        int p4 = idx & 3;
        int pos = i >> 4, c = i & 15;
        int ky = pos / 3, kx = pos % 3;
        const float4* src = reinterpret_cast<const float4*>(
            pose_in + ((((b * H_IN) + y + ky) * W_IN + (x + kx)) * 256 + c * 16));
        reinterpret_cast<float4*>(sm.pose)[i * 4 + p4] = src[p4];
    }
    // ---- Input activations ----
    for (int i = tid; i < ISZ; i += 256) {
        int pos = i >> 4, c = i & 15;
        int ky = pos / 3, kx = pos % 3;
        sm.act[i] = act_in[(((b * H_IN) + y + ky) * W_IN + (x + kx)) * OSZ + c];
    }
    // ---- Init routing ----
    for (int idx = tid; idx < ISZ * OSZ; idx += 256)
        sm.rr[idx] = 1.0f / 16.0f;
    __syncthreads();

    // ---- Vote transform: votes[i,o,pr,pc] = sum_q pose[i,pr,q] * w[i,o,q,pc] ----
    for (int pair = tid; pair < ISZ * OSZ; pair += 256) { // 9 pairs / thread
        int i = pair >> 4;
        const float4* wrow = reinterpret_cast<const float4*>(w + pair * 16);
        float4 w0 = wrow[0], w1 = wrow[1], w2 = wrow[2], w3 = wrow[3];
        const float* ps = sm.pose + i * 16;
        float4* vout = reinterpret_cast<float4*>(sm.votes + i * VSTRIDE + (pair & 15) * 16);
        #pragma unroll
        for (int pr = 0; pr < 4; pr++) {
            float a0 = ps[pr * 4 + 0], a1 = ps[pr * 4 + 1];
            float a2 = ps[pr * 4 + 2], a3 = ps[pr * 4 + 3];
            float4 r;
            r.x = a0 * w0.x + a1 * w1.x + a2 * w2.x + a3 * w3.x;
            r.y = a0 * w0.y + a1 * w1.y + a2 * w2.y + a3 * w3.y;
            r.z = a0 * w0.z + a1 * w1.z + a2 * w2.z + a3 * w3.z;
            r.w = a0 * w0.w + a1 * w1.w + a2 * w2.w + a3 * w3.w;
            vout[pr] = r;
        }
    }
    __syncthreads();

    // ---- EM routing: thread tid <-> (o = tid>>4, p = tid&15) ----
    const int o = tid >> 4;
    const int p = tid & 15;
    const float bv = beta_v[o];
    const float ba = beta_a[o];

    for (int it = 0; it < 3; it++) {
        const float inv_temp = 1.0f + (float)it;   // 1, 2, 3

        // rr_prime = rr * i_act
        for (int idx = tid; idx < ISZ * OSZ; idx += 256)
            sm.rp[idx] = sm.rr[idx] * sm.act[idx >> 4];
        __syncthreads();

        // M-step: per-(o,p) reduction over i
        float m = 0.0f, rs = 0.0f;
        #pragma unroll 4
        for (int i = 0; i < ISZ; i++) {
            float rp = sm.rp[i * OSZ + o];
            m  += rp * sm.votes[i * VSTRIDE + tid];
            rs += rp;
        }
        const float mean = m / (rs + EPSF);
        float s = 0.0f;
        #pragma unroll 4
        for (int i = 0; i < ISZ; i++) {
            float rp = sm.rp[i * OSZ + o];
            float d  = sm.votes[i * VSTRIDE + tid] - mean;
            s += rp * d * d;
        }
        const float stdv = sqrtf(s / (rs + EPSF));
        const float lstd = logf(stdv + EPSF);
        float csum = (bv + lstd) * rs;
        float lsum = lstd;
        #pragma unroll
        for (int off = 8; off; off >>= 1) {
            csum += __shfl_xor_sync(0xffffffffu, csum, off, 16);
            lsum += __shfl_xor_sync(0xffffffffu, lsum, off, 16);
        }
        sm.mean[tid]    = mean;
        sm.inv2var[tid] = 1.0f / (2.0f * stdv * stdv + EPSF);
        if (p == 0) {
            float a = 1.0f / (1.0f + expf(-inv_temp * (ba - csum)));
            sm.oact[o]   = a;
            sm.logact[o] = logf(a + EPSF);
            sm.slog[o]   = lsum;
            if (it == 2) out[NPOS * 256 + n * OSZ + o] = a;   // final activation
        }
        if (it == 2) {
            out[n * 256 + tid] = mean;                        // final pose
            break;
        }
        __syncthreads();

        // E-step: one thread per input capsule i
        if (tid < ISZ) {
            const int i = tid;
            float zz[OSZ];
            float zmax = -1e30f;
            #pragma unroll
            for (int oo = 0; oo < OSZ; oo++) {
                float acc = 0.0f;
                const float4* v4  = reinterpret_cast<const float4*>(sm.votes + i * VSTRIDE + oo * 16);
                const float4* m4  = reinterpret_cast<const float4*>(sm.mean + oo * 16);
                const float4* iv4 = reinterpret_cast<const float4*>(sm.inv2var + oo * 16);
                #pragma unroll
                for (int q = 0; q < 4; q++) {
                    float4 v = v4[q], mm = m4[q], iv = iv4[q];
                    float dx = v.x - mm.x, dy = v.y - mm.y;
                    float dz = v.z - mm.z, dw = v.w - mm.w;
                    acc += dx * dx * iv.x + dy * dy * iv.y + dz * dz * iv.z + dw * dw * iv.w;
                }
                float z = sm.logact[oo] - acc - sm.slog[oo];
                zz[oo] = z;
                zmax = fmaxf(zmax, z);
            }
            float esum = 0.0f;
            #pragma unroll
            for (int oo = 0; oo < OSZ; oo++) { zz[oo] = expf(zz[oo] - zmax); esum += zz[oo]; }
            const float inv = 1.0f / esum;
            #pragma unroll
            for (int oo = 0; oo < OSZ; oo++) sm.rr[i * OSZ + oo] = zz[oo] * inv;
        }
        __syncthreads();
    }
}

extern "C" void kernel_launch(void* const* d_in, const int* in_sizes, int n_in,
                              void* d_out, int out_size)
{
    const float* pose_in = (const float*)d_in[0];  // [8,14,14,256]
    const float* act_in  = (const float*)d_in[1];  // [8,14,14,16]
    const float* w       = (const float*)d_in[2];  // [144,16,4,4]
    const float* bv      = (const float*)d_in[3];  // [16]
    const float* ba      = (const float*)d_in[4];  // [16]
    float* out           = (float*)d_out;          // 1152*256 pose + 1152*16 act

    const int smem = (int)sizeof(Smem);
    cudaFuncSetAttribute(capsconv_em_kernel,
                         cudaFuncAttributeMaxDynamicSharedMemorySize, smem);
    capsconv_em_kernel<<<NPOS, 256, smem>>>(pose_in, act_in, w, bv, ba, out);
}

// round 2
// speedup vs baseline: 1.5539x; 1.5539x over previous
#include <cuda_runtime.h>
#include <math.h>

#define B_SZ   8
#define H_IN   14
#define W_IN   14
#define HP     12
#define WP     12
#define ISZ    144
#define OSZ    16
#define NPOS   (B_SZ * HP * WP)   // 1152
#define VSTRIDE 260               // 260 % 32 == 4 -> conflict-free LDS128 patterns
#define EPSF   1e-9f

struct Smem {
    float votes[ISZ * VSTRIDE];   // [i][o*16+p] (+pad)           149760 B
    float rrT[OSZ * ISZ];         // [o][i]                         9216 B
    float rpT[OSZ * ISZ];         // [o][i]                         9216 B
    float pose[ISZ * 16];         //                                9216 B
    float act[ISZ];               //                                 576 B
    float mean[256];              // [o*16+p]                        1024 B
    float iv[256];                // 1/(2 var + eps)                 1024 B
    float logact[OSZ];
    float slog[OSZ];
};
// ~180.3 KB

__global__ void __launch_bounds__(512, 1)
capsconv_em_kernel(const float* __restrict__ pose_in,   // [8,14,14,256]
                   const float* __restrict__ act_in,    // [8,14,14,16]
                   const float* __restrict__ w,         // [144,16,16]
                   const float* __restrict__ beta_v,    // [16]
                   const float* __restrict__ beta_a,    // [16]
                   float* __restrict__ out)             // pose[1152*256] ++ act[1152*16]
{
    extern __shared__ char smem_raw[];
    Smem& sm = *reinterpret_cast<Smem*>(smem_raw);

    const int tid = threadIdx.x;
    const int n   = blockIdx.x;
    const int b   = n / (HP * WP);
    const int rem = n % (HP * WP);
    const int y   = rem / WP;
    const int x   = rem % WP;

    // ---- Load pose patch (float4, coalesced) ----
    for (int idx = tid; idx < ISZ * 4; idx += 512) {
        int i  = idx >> 2;
        int p4 = idx & 3;
        int pos = i >> 4, c = i & 15;
        int ky = pos / 3, kx = pos % 3;
        const float4* src = reinterpret_cast<const float4*>(
            pose_in + ((((b * H_IN) + y + ky) * W_IN + (x + kx)) * 256 + c * 16));
        reinterpret_cast<float4*>(sm.pose)[i * 4 + p4] = src[p4];
    }
    // ---- Activations + rr init ----
    for (int i = tid; i < ISZ; i += 512) {
        int pos = i >> 4, c = i & 15;
        int ky = pos / 3, kx = pos % 3;
        sm.act[i] = act_in[(((b * H_IN) + y + ky) * W_IN + (x + kx)) * OSZ + c];
    }
    for (int idx = tid; idx < OSZ * ISZ; idx += 512)
        sm.rrT[idx] = 0.0625f;
    __syncthreads();

    // ---- Vote transform: votes[i][o][pr,:] = pose[i][pr,:] @ w[i][o] ----
    for (int pair = tid; pair < ISZ * OSZ; pair += 512) {
        int i = pair >> 4;
        const float4* wrow = reinterpret_cast<const float4*>(w + pair * 16);
        float4 w0 = wrow[0], w1 = wrow[1], w2 = wrow[2], w3 = wrow[3];
        const float* ps = sm.pose + i * 16;
        float4* vout = reinterpret_cast<float4*>(sm.votes + i * VSTRIDE + (pair & 15) * 16);
        #pragma unroll
        for (int pr = 0; pr < 4; pr++) {
            float a0 = ps[pr * 4 + 0], a1 = ps[pr * 4 + 1];
            float a2 = ps[pr * 4 + 2], a3 = ps[pr * 4 + 3];
            float4 r;
            r.x = fmaf(a0, w0.x, fmaf(a1, w1.x, fmaf(a2, w2.x, a3 * w3.x)));
            r.y = fmaf(a0, w0.y, fmaf(a1, w1.y, fmaf(a2, w2.y, a3 * w3.y)));
            r.z = fmaf(a0, w0.z, fmaf(a1, w1.z, fmaf(a2, w2.z, a3 * w3.z)));
            r.w = fmaf(a0, w0.w, fmaf(a1, w1.w, fmaf(a2, w2.w, a3 * w3.w)));
            vout[pr] = r;
        }
    }

    // ---- EM routing ----
    // M-step mapping: og = (o*4+pg) = tid>>3, chunk = tid&7; one o per warp.
    const int og    = tid >> 3;
    const int chunk = tid & 7;
    const int o     = og >> 2;             // == tid>>5 (warp id)
    const float bv  = beta_v[o];
    const float ba  = beta_a[o];
    const float* vptr = sm.votes + og * 4;
    const float* rpo  = sm.rpT + o * ISZ;

    for (int it = 0; it < 3; ++it) {
        // rr_prime (transposed): rpT[o][i] = rrT[o][i] * act[i]
        for (int idx = tid; idx < OSZ * ISZ; idx += 512)
            sm.rpT[idx] = sm.rrT[idx] * sm.act[idx % ISZ];
        __syncthreads();   // rp ready; also covers votes/rr writes of prev phase

        // Single-pass M-step stage 1: partial sums over i = chunk + 8*ii
        float m0=0.f,m1=0.f,m2=0.f,m3=0.f;
        float s0=0.f,s1=0.f,s2=0.f,s3=0.f;
        float rs=0.f;
        #pragma unroll 6
        for (int ii = 0; ii < 18; ++ii) {
            int i = chunk + (ii << 3);
            float rp = rpo[i];
            float4 v = *reinterpret_cast<const float4*>(vptr + i * VSTRIDE);
            m0 = fmaf(rp, v.x, m0);  s0 = fmaf(rp * v.x, v.x, s0);
            m1 = fmaf(rp, v.y, m1);  s1 = fmaf(rp * v.y, v.y, s1);
            m2 = fmaf(rp, v.z, m2);  s2 = fmaf(rp * v.z, v.z, s2);
            m3 = fmaf(rp, v.w, m3);  s3 = fmaf(rp * v.w, v.w, s3);
            rs += rp;
        }
        // Reduce over 8 chunk lanes (adjacent): butterfly
        #pragma unroll
        for (int off = 1; off < 8; off <<= 1) {
            m0 += __shfl_xor_sync(0xffffffffu, m0, off);
            m1 += __shfl_xor_sync(0xffffffffu, m1, off);
            m2 += __shfl_xor_sync(0xffffffffu, m2, off);
            m3 += __shfl_xor_sync(0xffffffffu, m3, off);
            s0 += __shfl_xor_sync(0xffffffffu, s0, off);
            s1 += __shfl_xor_sync(0xffffffffu, s1, off);
            s2 += __shfl_xor_sync(0xffffffffu, s2, off);
            s3 += __shfl_xor_sync(0xffffffffu, s3, off);
            rs += __shfl_xor_sync(0xffffffffu, rs, off);
        }
        const float inv_r = __fdividef(1.0f, rs + EPSF);
        const float me0 = m0 * inv_r, me1 = m1 * inv_r;
        const float me2 = m2 * inv_r, me3 = m3 * inv_r;
        // e = s - 2*mean*m + mean^2*rs  (>=0 clamp), var = e/rs
        float e0 = fmaf(me0, fmaf(me0, rs, -2.0f * m0), s0);
        float e1 = fmaf(me1, fmaf(me1, rs, -2.0f * m1), s1);
        float e2 = fmaf(me2, fmaf(me2, rs, -2.0f * m2), s2);
        float e3 = fmaf(me3, fmaf(me3, rs, -2.0f * m3), s3);
        float v0 = fmaxf(e0, 0.f) * inv_r, v1 = fmaxf(e1, 0.f) * inv_r;
        float v2 = fmaxf(e2, 0.f) * inv_r, v3 = fmaxf(e3, 0.f) * inv_r;
        float l0 = __logf(sqrtf(v0) + EPSF), l1 = __logf(sqrtf(v1) + EPSF);
        float l2 = __logf(sqrtf(v2) + EPSF), l3 = __logf(sqrtf(v3) + EPSF);
        float lsum = (l0 + l1) + (l2 + l3);
        lsum += __shfl_xor_sync(0xffffffffu, lsum, 8);
        lsum += __shfl_xor_sync(0xffffffffu, lsum, 16);   // sum over all 16 p

        const float inv_temp = 1.0f + (float)it;
        const float cost = fmaf(16.0f, bv, lsum) * rs;
        const float a = __fdividef(1.0f, 1.0f + __expf(-inv_temp * (ba - cost)));

        if (it == 2) {
            if (chunk == 0) {
                float4 mn = make_float4(me0, me1, me2, me3);
                *reinterpret_cast<float4*>(out + n * 256 + og * 4) = mn;
            }
            if ((tid & 31) == 0)
                out[NPOS * 256 + n * OSZ + o] = a;
            return;
        }

        if (chunk == 0) {
            *reinterpret_cast<float4*>(sm.mean + og * 4) = make_float4(me0, me1, me2, me3);
            float4 ivv;
            ivv.x = __fdividef(1.0f, 2.0f * v0 + EPSF);
            ivv.y = __fdividef(1.0f, 2.0f * v1 + EPSF);
            ivv.z = __fdividef(1.0f, 2.0f * v2 + EPSF);
            ivv.w = __fdividef(1.0f, 2.0f * v3 + EPSF);
            *reinterpret_cast<float4*>(sm.iv + og * 4) = ivv;
        }
        if ((tid & 31) == 0) {
            sm.logact[o] = __logf(a + EPSF);
            sm.slog[o]   = lsum;
        }
        __syncthreads();   // mean/iv/logact/slog ready

        // E-step: 288 threads = (i, half g); oo = 2j + g keeps banks disjoint
        if (tid < 2 * ISZ) {
            const int i = tid >> 1;
            const int g = tid & 1;
            const float* vb = sm.votes + i * VSTRIDE;
            float zz[8];
            float zmax = -1e30f;
            #pragma unroll
            for (int j = 0; j < 8; ++j) {
                int oo = (j << 1) + g;
                const float4* v4  = reinterpret_cast<const float4*>(vb + oo * 16);
                const float4* m4  = reinterpret_cast<const float4*>(sm.mean + oo * 16);
                const float4* iv4 = reinterpret_cast<const float4*>(sm.iv + oo * 16);
                float acc = 0.f;
                #pragma unroll
                for (int q = 0; q < 4; ++q) {
                    float4 v = v4[q], mm = m4[q], iv = iv4[q];
                    float dx = v.x - mm.x, dy = v.y - mm.y;
                    float dz = v.z - mm.z, dw = v.w - mm.w;
                    acc = fmaf(dx * dx, iv.x, acc);
                    acc = fmaf(dy * dy, iv.y, acc);
                    acc = fmaf(dz * dz, iv.z, acc);
                    acc = fmaf(dw * dw, iv.w, acc);
                }
                float z = sm.logact[oo] - acc - sm.slog[oo];
                zz[j] = z;
                zmax = fmaxf(zmax, z);
            }
            zmax = fmaxf(zmax, __shfl_xor_sync(0xffffffffu, zmax, 1));
            float es = 0.f;
            #pragma unroll
            for (int j = 0; j < 8; ++j) { zz[j] = __expf(zz[j] - zmax); es += zz[j]; }
            es += __shfl_xor_sync(0xffffffffu, es, 1);
            const float inv = __fdividef(1.0f, es);
            #pragma unroll
            for (int j = 0; j < 8; ++j)
                sm.rrT[((j << 1) + g) * ISZ + i] = zz[j] * inv;
        }
        __syncthreads();   // rr ready for next iteration
    }
}

extern "C" void kernel_launch(void* const* d_in, const int* in_sizes, int n_in,
                              void* d_out, int out_size)
{
    const float* pose_in = (const float*)d_in[0];
    const float* act_in  = (const float*)d_in[1];
    const float* w       = (const float*)d_in[2];
    const float* bv      = (const float*)d_in[3];
    const float* ba      = (const float*)d_in[4];
    float* out           = (float*)d_out;

    const int smem = (int)sizeof(Smem);
    cudaFuncSetAttribute(capsconv_em_kernel,
                         cudaFuncAttributeMaxDynamicSharedMemorySize, smem);
    capsconv_em_kernel<<<NPOS, 512, smem>>>(pose_in, act_in, w, bv, ba, out);
}